// round 16
// baseline (speedup 1.0000x reference)
#include <cuda_runtime.h>
#include <cuda_fp16.h>
#include <cstdint>
#include <cstddef>

#define NB 1024
#define NT 512
#define NH 128
#define BT (NB * NT)
#define GRP 49     // batch groups
#define MBB 21     // batches per group (last group 16)

// ---------------- scratch (device globals; no runtime allocation) ----------------
__device__ __half g_h0[(size_t)NB * NT * NH];   // layer0 out fp16 [B][T][H]
__device__ __half g_h1[(size_t)NB * NT * NH];   // layer1 out fp16 [B][T][H]
__device__ float  g_hlast[NB * NH];             // layer2 last h (fp32)
__device__ __half g_xph[(size_t)BT * 512];      // layer0 x-projection fp16 (bias incl)
__device__ __half g_WC0[65536];                 // layer0 w_hh  frag pack (K=128)
__device__ __half g_WC1[131072];                // layer1 [w_ih|w_hh] frag pack (K=256)
__device__ __half g_WC2[131072];                // layer2 [w_ih|w_hh] frag pack (K=256)
__device__ float  g_biasxp[3][512];             // bias, c = u*4+q order
__device__ float  g_w0p[512 * 8];               // layer0 w_ih packed [c][8] (k<6)
__device__ int    g_flag[128];                  // [layer(0,1)*64 + group] handoff flags

// ---------------- activations / helpers ----------------
__device__ __forceinline__ float fast_tanh(float x) {
    float y;
    asm("tanh.approx.f32 %0, %1;" : "=f"(y) : "f"(x));
    return y;
}
__device__ __forceinline__ float fast_sig(float x) {
    return fmaf(0.5f, fast_tanh(0.5f * x), 0.5f);
}
__device__ __forceinline__ uint32_t smem_u32(const void* p) {
    uint32_t a;
    asm("{ .reg .u64 t; cvta.to.shared.u64 t, %1; cvt.u32.u64 %0, t; }" : "=r"(a) : "l"(p));
    return a;
}

// ---------------- prep: K=128 frag pack (layer0 w_hh) + bias ----------------
__global__ void prep_mma_kernel(const float* __restrict__ W,
                                const float* __restrict__ b_ih,
                                const float* __restrict__ b_hh,
                                __half* __restrict__ WF, float* __restrict__ bias)
{
    for (int idx = blockIdx.x * blockDim.x + threadIdx.x; idx < 65536;
         idx += gridDim.x * blockDim.x) {
        int h4   = idx & 3;
        int lane = (idx >> 2) & 31;
        int ks   = (idx >> 7) & 7;
        int cb   = idx >> 10;
        int c = cb * 8 + (lane >> 2);
        int q = c & 3, u = c >> 2;
        int g = q * NH + u;
        int k = ks * 16 + (lane & 3) * 2 + (h4 & 1) + (h4 >> 1) * 8;
        WF[idx] = __float2half(W[g * NH + k]);
    }
    for (int c = blockIdx.x * blockDim.x + threadIdx.x; c < 512;
         c += gridDim.x * blockDim.x) {
        int q = c & 3, u = c >> 2;
        int g = q * NH + u;
        bias[c] = b_ih[g] + b_hh[g];
    }
}

// ---------------- prep: K=256 frag pack ([w_ih | w_hh]) + bias ----------------
__global__ void prep256_kernel(const float* __restrict__ wih,
                               const float* __restrict__ whh,
                               const float* __restrict__ b_ih,
                               const float* __restrict__ b_hh,
                               __half* __restrict__ WC, float* __restrict__ bias)
{
    for (int idx = blockIdx.x * blockDim.x + threadIdx.x; idx < 131072;
         idx += gridDim.x * blockDim.x) {
        int h4   = idx & 3;
        int lane = (idx >> 2) & 31;
        int ks   = (idx >> 7) & 15;
        int cb   = idx >> 11;
        int c = cb * 8 + (lane >> 2);
        int q = c & 3, u = c >> 2;
        int g = q * NH + u;
        int k = ks * 16 + (lane & 3) * 2 + (h4 & 1) + (h4 >> 1) * 8;
        float val = (k < 128) ? wih[g * NH + k] : whh[g * NH + (k - 128)];
        WC[idx] = __float2half(val);
    }
    for (int c = blockIdx.x * blockDim.x + threadIdx.x; c < 512;
         c += gridDim.x * blockDim.x) {
        int q = c & 3, u = c >> 2;
        int g = q * NH + u;
        bias[c] = b_ih[g] + b_hh[g];
    }
}

// ---------------- prep: layer0 w_ih pack (K=6) + bias ----------------
__global__ void prep_l0_kernel(const float* __restrict__ w_ih,
                               const float* __restrict__ b_ih,
                               const float* __restrict__ b_hh,
                               float* __restrict__ w0p, float* __restrict__ bias)
{
    for (int idx = blockIdx.x * blockDim.x + threadIdx.x; idx < 512 * 8;
         idx += gridDim.x * blockDim.x) {
        int k = idx & 7, c = idx >> 3;
        int q = c & 3, u = c >> 2;
        int g = q * NH + u;
        w0p[idx] = (k < 6) ? w_ih[g * 6 + k] : 0.0f;
    }
    for (int c = blockIdx.x * blockDim.x + threadIdx.x; c < 512;
         c += gridDim.x * blockDim.x) {
        int q = c & 3, u = c >> 2;
        int g = q * NH + u;
        bias[c] = b_ih[g] + b_hh[g];
    }
}

// ---------------- flag reset (every launch; graph-capturable) ----------------
__global__ void flag_reset_kernel()
{
    if (threadIdx.x < 128) g_flag[threadIdx.x] = 0;
}

// ---------------- layer0 x-projection (scalar, K=6) -> fp16, bias included ----
__global__ void __launch_bounds__(512, 1)
xp0_kernel(const float* __restrict__ x, const float* __restrict__ w0p,
           const float* __restrict__ bias, __half* __restrict__ XP)
{
    __shared__ __align__(16) float xs[128 * 8];
    const int tid = threadIdx.x;
    const size_t row0 = (size_t)blockIdx.x * 128;

    for (int i = tid; i < 1024; i += 512) {
        int r = i >> 3, k = i & 7;
        xs[i] = (k < 6) ? x[(row0 + r) * 6 + k] : 0.0f;
    }
    __syncthreads();

    const int c = tid;
    float4 w01 = *reinterpret_cast<const float4*>(&w0p[c * 8]);
    float4 w23 = *reinterpret_cast<const float4*>(&w0p[c * 8 + 4]);
    float bc = bias[c];
    for (int r = 0; r < 128; ++r) {
        float4 x01 = *reinterpret_cast<const float4*>(&xs[r * 8]);
        float2 x2  = *reinterpret_cast<const float2*>(&xs[r * 8 + 4]);
        float s = bc;
        s = fmaf(w01.x, x01.x, s);
        s = fmaf(w01.y, x01.y, s);
        s = fmaf(w01.z, x01.z, s);
        s = fmaf(w01.w, x01.w, s);
        s = fmaf(w23.x, x2.x, s);
        s = fmaf(w23.y, x2.y, s);
        XP[(row0 + r) * 512 + c] = __float2half(s);
    }
}

// ---------------- fused mma block (KS k-steps over A tile rows 0..31) ----------
template <int KS>
__device__ __forceinline__ void mma_block(uint32_t Ab, const uint2* __restrict__ WC,
                                          int wid, int lane, float acc[2][4][4])
{
    const int cb0  = wid * 4;
    const int lrow = (lane & 7) + ((lane >> 3) & 1) * 8;
    const int kadd = (lane >> 4) * 8;
#pragma unroll
    for (int ks = 0; ks < KS; ++ks) {
        uint2 bf[4];
#pragma unroll
        for (int nt = 0; nt < 4; ++nt)
            bf[nt] = WC[(size_t)((cb0 + nt) * KS + ks) * 32 + lane];
#pragma unroll
        for (int mt = 0; mt < 2; ++mt) {
            uint32_t addr = Ab + (uint32_t)((mt * 16 + lrow) * 264 + ks * 16 + kadd) * 2;
            uint32_t a0, a1, a2, a3;
            asm volatile("ldmatrix.sync.aligned.m8n8.x4.shared.b16 {%0,%1,%2,%3}, [%4];"
                         : "=r"(a0), "=r"(a1), "=r"(a2), "=r"(a3) : "r"(addr));
#pragma unroll
            for (int nt = 0; nt < 4; ++nt) {
                asm volatile(
                    "mma.sync.aligned.m16n8k16.row.col.f32.f16.f16.f32 "
                    "{%0,%1,%2,%3}, {%4,%5,%6,%7}, {%8,%9}, {%0,%1,%2,%3};"
                    : "+f"(acc[mt][nt][0]), "+f"(acc[mt][nt][1]),
                      "+f"(acc[mt][nt][2]), "+f"(acc[mt][nt][3])
                    : "r"(a0), "r"(a1), "r"(a2), "r"(a3),
                      "r"(bf[nt].x), "r"(bf[nt].y));
            }
        }
    }
}

// ---------------- fused 3-layer pipelined LSTM ----------------
// 147 CTAs = 3 layers x 49 groups of 21 batches; all co-resident.
// A tile [32 rows x 264 halves]: rows = batches (21 used), K = [h_prev | h_own]
// (layers 1,2; K=256) or [h_own] (layer0; K=128). Per step: stage h_prev
// (spin on producer flag) -> sync -> mma (fp32 acc) -> Dsm -> sync ->
// pointwise (6 cells/thread) -> h into A + gmem -> fence/sync -> publish flag.
__global__ void __launch_bounds__(512, 1)
fused_lstm_kernel(const __half* __restrict__ xp0,    // [BT][512] layer0 xproj
                  const __half* __restrict__ WC0,
                  const __half* __restrict__ WC1,
                  const __half* __restrict__ WC2,
                  const float* __restrict__ bias1,
                  const float* __restrict__ bias2,
                  __half* __restrict__ h0buf,
                  __half* __restrict__ h1buf,
                  float* __restrict__ hlast)
{
    extern __shared__ __align__(16) char sm[];
    __half* A    = reinterpret_cast<__half*>(sm);                 // 32*264 halves
    __half* Dsm  = reinterpret_cast<__half*>(sm + 16896);         // 32*520 halves
    float*  sb   = reinterpret_cast<float*>(sm + 16896 + 33280);  // 512 floats

    const int tid  = threadIdx.x;
    const int wid  = tid >> 5;
    const int lane = tid & 31;
    const int layer = blockIdx.x / GRP;
    const int grp   = blockIdx.x - layer * GRP;
    const int b0 = grp * MBB;
    const int nb = (NB - b0 < MBB) ? (NB - b0) : MBB;

    const uint2* WC = reinterpret_cast<const uint2*>(
        layer == 0 ? WC0 : (layer == 1 ? WC1 : WC2));
    const __half* hprev = (layer == 1) ? h0buf : h1buf;   // layer0 unused
    __half* hout = (layer == 0) ? h0buf : ((layer == 1) ? h1buf : nullptr);
    volatile int* flag_in  = (layer > 0) ? (volatile int*)&g_flag[(layer - 1) * 64 + grp] : nullptr;
    int* flag_out = (layer < 2) ? &g_flag[layer * 64 + grp] : nullptr;

    // load bias to smem (layers 1,2)
    if (layer > 0 && tid < 128) {
        const float* bsrc = (layer == 1) ? bias1 : bias2;
        reinterpret_cast<float4*>(sb)[tid] =
            reinterpret_cast<const float4*>(bsrc)[tid];
    }
    // zero A tile
    for (int i = tid; i < 32 * 264 / 2; i += 512)
        reinterpret_cast<uint32_t*>(A)[i] = 0u;
    __syncthreads();

    const uint32_t Ab = smem_u32(A);
    const int gp  = lane >> 2;
    const int tig = lane & 3;
    const int kg  = tid >> 7;     // epilogue role
    const int u   = tid & 127;

    float cst[6];
#pragma unroll
    for (int i = 0; i < 6; ++i) cst[i] = 0.f;

    for (int t = 0; t < NT; ++t) {
        // ---- wait for producer + stage h_prev into A cols [0,128) ----
        if (layer > 0) {
            const int target = t + 1;
            while (*flag_in < target) {}
            __threadfence();
            for (int i = tid; i < nb * 16; i += 512) {
                int bl = i >> 4, v = i & 15;
                uint4 d = reinterpret_cast<const uint4*>(
                    &hprev[((size_t)(b0 + bl) * NT + t) * NH])[v];
                reinterpret_cast<uint4*>(
                    reinterpret_cast<char*>(A) + bl * 528)[v] = d;
            }
        }
        // ---- layer0: prefetch xp quads for 6 cells ----
        uint2 xq[6];
        if (layer == 0) {
#pragma unroll
            for (int i = 0; i < 6; ++i) {
                int r = kg + 4 * i;
                xq[i] = make_uint2(0u, 0u);
                if (r < nb)
                    xq[i] = *reinterpret_cast<const uint2*>(
                        &xp0[((size_t)(b0 + r) * NT + t) * 512 + u * 4]);
            }
        }
        __syncthreads();   // A complete (h_prev staged + h_own from prev step)

        // ---- gates GEMM ----
        float acc[2][4][4];
#pragma unroll
        for (int mt = 0; mt < 2; ++mt)
#pragma unroll
            for (int nt = 0; nt < 4; ++nt)
#pragma unroll
                for (int i = 0; i < 4; ++i) acc[mt][nt][i] = 0.f;

        if (layer == 0) mma_block<8>(Ab, WC, wid, lane, acc);
        else            mma_block<16>(Ab, WC, wid, lane, acc);

        // ---- store D to Dsm: rows mt*16+gp (c0,c1) and +8 (c2,c3) ----
#pragma unroll
        for (int mt = 0; mt < 2; ++mt)
#pragma unroll
            for (int nt = 0; nt < 4; ++nt) {
                int col = (wid * 4 + nt) * 8 + tig * 2;
                int r0 = mt * 16 + gp;
                *reinterpret_cast<__half2*>(&Dsm[r0 * 520 + col]) =
                    __floats2half2_rn(acc[mt][nt][0], acc[mt][nt][1]);
                *reinterpret_cast<__half2*>(&Dsm[(r0 + 8) * 520 + col]) =
                    __floats2half2_rn(acc[mt][nt][2], acc[mt][nt][3]);
            }
        __syncthreads();   // Dsm ready; A reads done

        // ---- pointwise: 6 cells (rows kg+4i) for unit u ----
        float4 bias4 = make_float4(0.f, 0.f, 0.f, 0.f);
        if (layer > 0) bias4 = reinterpret_cast<const float4*>(sb)[u];
        const int hcol = (layer == 0) ? u : 128 + u;
#pragma unroll
        for (int i = 0; i < 6; ++i) {
            const int r = kg + 4 * i;
            uint2 d2 = *reinterpret_cast<const uint2*>(&Dsm[r * 520 + u * 4]);
            float2 d01 = __half22float2(reinterpret_cast<const __half2*>(&d2)[0]);
            float2 d23 = __half22float2(reinterpret_cast<const __half2*>(&d2)[1]);
            float gi, gf, gg, go;
            if (layer == 0) {
                float2 x01 = __half22float2(reinterpret_cast<const __half2*>(&xq[i])[0]);
                float2 x23 = __half22float2(reinterpret_cast<const __half2*>(&xq[i])[1]);
                gi = d01.x + x01.x; gf = d01.y + x01.y;
                gg = d23.x + x23.x; go = d23.y + x23.y;
            } else {
                gi = d01.x + bias4.x; gf = d01.y + bias4.y;
                gg = d23.x + bias4.z; go = d23.y + bias4.w;
            }
            float ii = fast_sig(gi);
            float ff = fast_sig(gf);
            float gz = fast_tanh(gg);
            float oo = fast_sig(go);
            float cn = fmaf(ff, cst[i], ii * gz);
            cst[i] = cn;
            float hn = oo * fast_tanh(cn);
            __half hn16 = __float2half(hn);

            A[r * 264 + hcol] = hn16;
            if (r < nb) {
                if (hout)
                    hout[((size_t)(b0 + r) * NT + t) * NH + u] = hn16;
                if (layer == 2 && t == NT - 1)
                    hlast[(b0 + r) * NH + u] = hn;
            }
        }

        // ---- publish ----
        if (layer < 2) __threadfence();
        __syncthreads();
        if (layer < 2 && tid == 0)
            *(volatile int*)flag_out = t + 1;
    }
}

// ---------------- final FC on last timestep of layer 2 ----------------
__global__ void fc_kernel(const float* __restrict__ fc_w,
                          const float* __restrict__ fc_b,
                          float* __restrict__ out)
{
    int b = blockIdx.x;
    int tid = threadIdx.x;
    float p = g_hlast[b * NH + tid] * fc_w[tid];
#pragma unroll
    for (int o = 16; o; o >>= 1) p += __shfl_down_sync(0xffffffffu, p, o);
    __shared__ float ws[4];
    if ((tid & 31) == 0) ws[tid >> 5] = p;
    __syncthreads();
    if (tid == 0) out[b] = ws[0] + ws[1] + ws[2] + ws[3] + fc_b[0];
}

// ---------------- launch ----------------
extern "C" void kernel_launch(void* const* d_in, const int* in_sizes, int n_in,
                              void* d_out, int out_size)
{
    const float* x    = (const float*)d_in[0];
    const float* wih0 = (const float*)d_in[1];
    const float* whh0 = (const float*)d_in[2];
    const float* bih0 = (const float*)d_in[3];
    const float* bhh0 = (const float*)d_in[4];
    const float* wih1 = (const float*)d_in[5];
    const float* whh1 = (const float*)d_in[6];
    const float* bih1 = (const float*)d_in[7];
    const float* bhh1 = (const float*)d_in[8];
    const float* wih2 = (const float*)d_in[9];
    const float* whh2 = (const float*)d_in[10];
    const float* bih2 = (const float*)d_in[11];
    const float* bhh2 = (const float*)d_in[12];
    const float* fcw  = (const float*)d_in[13];
    const float* fcb  = (const float*)d_in[14];
    float* out = (float*)d_out;

    void *ph0, *ph1, *phl, *pxp, *pwc0, *pwc1, *pwc2, *pbias, *pw0;
    cudaGetSymbolAddress(&ph0, g_h0);
    cudaGetSymbolAddress(&ph1, g_h1);
    cudaGetSymbolAddress(&phl, g_hlast);
    cudaGetSymbolAddress(&pxp, g_xph);
    cudaGetSymbolAddress(&pwc0, g_WC0);
    cudaGetSymbolAddress(&pwc1, g_WC1);
    cudaGetSymbolAddress(&pwc2, g_WC2);
    cudaGetSymbolAddress(&pbias, g_biasxp);
    cudaGetSymbolAddress(&pw0, g_w0p);

    __half* h0  = (__half*)ph0;
    __half* h1  = (__half*)ph1;
    float*  hl  = (float*)phl;
    __half* xp  = (__half*)pxp;
    float*  bs  = (float*)pbias;
    float*  w0p = (float*)pw0;

    const int fused_smem = 16896 + 33280 + 2048;   // 52224
    cudaFuncSetAttribute((const void*)fused_lstm_kernel,
                         cudaFuncAttributeMaxDynamicSharedMemorySize, fused_smem);

    // prep
    prep_l0_kernel <<<64, 256>>>(wih0, bih0, bhh0, w0p, bs + 0 * 512);
    prep_mma_kernel<<<132, 256>>>(whh0, bih0, bhh0, (__half*)pwc0, bs + 0 * 512);
    prep256_kernel <<<132, 256>>>(wih1, whh1, bih1, bhh1, (__half*)pwc1, bs + 1 * 512);
    prep256_kernel <<<132, 256>>>(wih2, whh2, bih2, bhh2, (__half*)pwc2, bs + 2 * 512);

    // layer0 x-projection (bias folded)
    xp0_kernel<<<BT / 128, 512>>>(x, w0p, bs + 0 * 512, xp);

    // fused pipelined 3-layer recurrence
    flag_reset_kernel<<<1, 128>>>();
    fused_lstm_kernel<<<3 * GRP, 512, fused_smem>>>(
        xp, (const __half*)pwc0, (const __half*)pwc1, (const __half*)pwc2,
        bs + 1 * 512, bs + 2 * 512, h0, h1, hl);

    fc_kernel<<<NB, 128>>>(fcw, fcb, out);
}

// round 17
// speedup vs baseline: 1.0016x; 1.0016x over previous
#include <cuda_runtime.h>
#include <cuda_fp16.h>
#include <cstdint>
#include <cstddef>

#define NB 1024
#define NT 512
#define NH 128
#define BT (NB * NT)
#define NBC 7   // batches per rec CTA

// ---------------- scratch (device globals; no runtime allocation) ----------------
__device__ __half g_h0[(size_t)NB * NT * NH];   // layer0 out fp16 [B][T][H]
__device__ __half g_h1[(size_t)NB * NT * NH];   // layer1 out fp16 [B][T][H]
__device__ float  g_hlast[NB * NH];             // layer2 last h (fp32)
__device__ __half g_xph[(size_t)BT * 512];      // x-projection fp16 (reused per layer)
__device__ __half g_WF[2][65536];               // mma frag-packed w_ih (layers 1,2)
__device__ __half g_WR[3][65536];               // mma frag-packed w_hh (all layers)
__device__ float  g_biasxp[3][512];             // per-layer bias (c = u*4+q order)
__device__ float  g_w0p[512 * 8];               // layer0 w_ih packed [c][8] (k<6)

// ---------------- activations / helpers ----------------
__device__ __forceinline__ float fast_tanh(float x) {
    float y;
    asm("tanh.approx.f32 %0, %1;" : "=f"(y) : "f"(x));
    return y;
}
__device__ __forceinline__ float fast_sig(float x) {
    return fmaf(0.5f, fast_tanh(0.5f * x), 0.5f);
}
__device__ __forceinline__ uint32_t smem_u32(const void* p) {
    uint32_t a;
    asm("{ .reg .u64 t; cvta.to.shared.u64 t, %1; cvt.u32.u64 %0, t; }" : "=r"(a) : "l"(p));
    return a;
}

// ---------------- prep: mma B-frag pack for a [512,128] matrix + bias ----------
__global__ void prep_mma_kernel(const float* __restrict__ W,
                                const float* __restrict__ b_ih,
                                const float* __restrict__ b_hh,
                                __half* __restrict__ WF, float* __restrict__ bias)
{
    for (int idx = blockIdx.x * blockDim.x + threadIdx.x; idx < 65536;
         idx += gridDim.x * blockDim.x) {
        int h4   = idx & 3;
        int lane = (idx >> 2) & 31;
        int ks   = (idx >> 7) & 7;
        int cb   = idx >> 10;
        int c = cb * 8 + (lane >> 2);
        int q = c & 3, u = c >> 2;
        int g = q * NH + u;
        int k = ks * 16 + (lane & 3) * 2 + (h4 & 1) + (h4 >> 1) * 8;
        WF[idx] = __float2half(W[g * NH + k]);
    }
    for (int c = blockIdx.x * blockDim.x + threadIdx.x; c < 512;
         c += gridDim.x * blockDim.x) {
        int q = c & 3, u = c >> 2;
        int g = q * NH + u;
        bias[c] = b_ih[g] + b_hh[g];
    }
}

// ---------------- prep: layer0 w_ih pack (K=6) + bias ----------------
__global__ void prep_l0_kernel(const float* __restrict__ w_ih,
                               const float* __restrict__ b_ih,
                               const float* __restrict__ b_hh,
                               float* __restrict__ w0p, float* __restrict__ bias)
{
    for (int idx = blockIdx.x * blockDim.x + threadIdx.x; idx < 512 * 8;
         idx += gridDim.x * blockDim.x) {
        int k = idx & 7, c = idx >> 3;
        int q = c & 3, u = c >> 2;
        int g = q * NH + u;
        w0p[idx] = (k < 6) ? w_ih[g * 6 + k] : 0.0f;
    }
    for (int c = blockIdx.x * blockDim.x + threadIdx.x; c < 512;
         c += gridDim.x * blockDim.x) {
        int q = c & 3, u = c >> 2;
        int g = q * NH + u;
        bias[c] = b_ih[g] + b_hh[g];
    }
}

// ---------------- layer0 x-projection (scalar, K=6) -> fp16 ----------------
__global__ void __launch_bounds__(512, 1)
xp0_kernel(const float* __restrict__ x, const float* __restrict__ w0p,
           const float* __restrict__ bias, __half* __restrict__ XP)
{
    __shared__ __align__(16) float xs[128 * 8];
    const int tid = threadIdx.x;
    const size_t row0 = (size_t)blockIdx.x * 128;

    for (int i = tid; i < 1024; i += 512) {
        int r = i >> 3, k = i & 7;
        xs[i] = (k < 6) ? x[(row0 + r) * 6 + k] : 0.0f;
    }
    __syncthreads();

    const int c = tid;
    float4 w01 = *reinterpret_cast<const float4*>(&w0p[c * 8]);
    float4 w23 = *reinterpret_cast<const float4*>(&w0p[c * 8 + 4]);
    float bc = bias[c];
    for (int r = 0; r < 128; ++r) {
        float4 x01 = *reinterpret_cast<const float4*>(&xs[r * 8]);
        float2 x2  = *reinterpret_cast<const float2*>(&xs[r * 8 + 4]);
        float s = bc;
        s = fmaf(w01.x, x01.x, s);
        s = fmaf(w01.y, x01.y, s);
        s = fmaf(w01.z, x01.z, s);
        s = fmaf(w01.w, x01.w, s);
        s = fmaf(w23.x, x2.x, s);
        s = fmaf(w23.y, x2.y, s);
        XP[(row0 + r) * 512 + c] = __float2half(s);
    }
}

// ---------------- layers 1,2 x-projection via mma.sync -> fp16 ----------------
__global__ void __launch_bounds__(512, 1)
xp_mma_kernel(const __half* __restrict__ X, const __half* __restrict__ WF,
              const float* __restrict__ bias, __half* __restrict__ XP)
{
    __shared__ __align__(16) __half xs[128 * 136];
    const int tid  = threadIdx.x;
    const int wid  = tid >> 5;
    const int lane = tid & 31;
    const size_t row0 = (size_t)blockIdx.x * 128;
    const int ny = blockIdx.y;

    for (int i = tid; i < 2048; i += 512) {
        int r = i >> 4, cvec = i & 15;
        reinterpret_cast<uint4*>(xs)[r * 17 + cvec] =
            reinterpret_cast<const uint4*>(X + (row0 + r) * NH)[cvec];
    }
    __syncthreads();

    const int wm = wid & 3;
    const int wn = wid >> 2;
    const int cb0 = ny * 32 + wn * 8;
    const uint2* __restrict__ WFp = reinterpret_cast<const uint2*>(WF);

    const int lrow = (lane & 7) + ((lane >> 3) & 1) * 8;
    const int kadd = (lane >> 4) * 8;
    const uint32_t xsb = smem_u32(xs);

    float acc[2][8][4];
#pragma unroll
    for (int mt = 0; mt < 2; ++mt)
#pragma unroll
        for (int nt = 0; nt < 8; ++nt)
#pragma unroll
            for (int i = 0; i < 4; ++i) acc[mt][nt][i] = 0.0f;

#pragma unroll
    for (int ks = 0; ks < 8; ++ks) {
        uint2 b[8];
#pragma unroll
        for (int nt = 0; nt < 8; ++nt)
            b[nt] = WFp[(size_t)((cb0 + nt) * 8 + ks) * 32 + lane];

#pragma unroll
        for (int mt = 0; mt < 2; ++mt) {
            int row = wm * 32 + mt * 16 + lrow;
            uint32_t addr = xsb + (uint32_t)(row * 136 + ks * 16 + kadd) * 2;
            uint32_t a0, a1, a2, a3;
            asm volatile("ldmatrix.sync.aligned.m8n8.x4.shared.b16 {%0,%1,%2,%3}, [%4];"
                         : "=r"(a0), "=r"(a1), "=r"(a2), "=r"(a3) : "r"(addr));
#pragma unroll
            for (int nt = 0; nt < 8; ++nt) {
                asm volatile(
                    "mma.sync.aligned.m16n8k16.row.col.f32.f16.f16.f32 "
                    "{%0,%1,%2,%3}, {%4,%5,%6,%7}, {%8,%9}, {%0,%1,%2,%3};"
                    : "+f"(acc[mt][nt][0]), "+f"(acc[mt][nt][1]),
                      "+f"(acc[mt][nt][2]), "+f"(acc[mt][nt][3])
                    : "r"(a0), "r"(a1), "r"(a2), "r"(a3),
                      "r"(b[nt].x), "r"(b[nt].y));
            }
        }
    }

    const int gp = lane >> 2, tig = lane & 3;
#pragma unroll
    for (int mt = 0; mt < 2; ++mt) {
#pragma unroll
        for (int nt = 0; nt < 8; ++nt) {
            size_t row = row0 + wm * 32 + mt * 16 + gp;
            int col = ny * 256 + wn * 64 + nt * 8 + tig * 2;
            float2 bb = *reinterpret_cast<const float2*>(&bias[col]);
            __half2 o0 = __floats2half2_rn(acc[mt][nt][0] + bb.x, acc[mt][nt][1] + bb.y);
            __half2 o1 = __floats2half2_rn(acc[mt][nt][2] + bb.x, acc[mt][nt][3] + bb.y);
            *reinterpret_cast<__half2*>(&XP[row * 512 + col]) = o0;
            *reinterpret_cast<__half2*>(&XP[(row + 8) * 512 + col]) = o1;
        }
    }
}

// ---------------- recurrent LSTM layer via mma.sync, 1024 threads ----------------
// 147 CTAs x 1024 thr (8 warps/SMSP for latency hiding); CTA = 7 batches in one
// m16 tile. Warp owns 2 n8 tiles (16 gate cols): 8 ldmatrix.x4 + 16 mma
// (fp32 acc) per step; B-frags streamed from gmem (L1-hot) to stay <=64 regs.
// D rows 0..7 -> Dsm fp16; epilogue: 896 threads x 1 cell. Two syncs/step;
// xp prefetched one step ahead.
__global__ void __launch_bounds__(1024, 1)
rec_mma_kernel(const __half* __restrict__ xp,     // [BT][512] fp16, bias included
               const __half* __restrict__ WR,     // frag-packed w_hh
               __half* __restrict__ hout,         // [B][T][128] or nullptr
               float* __restrict__ hlast)         // [B][128] or nullptr
{
    __shared__ __align__(16) __half A[2][16 * 136];   // double-buffered h tile
    __shared__ __align__(16) __half Dsm[8 * 520];     // gate pre-acts rows 0..7

    const int tid  = threadIdx.x;
    const int wid  = tid >> 5;           // 0..31
    const int lane = tid & 31;
    const int b0   = blockIdx.x * NBC;
    const int nb   = (NB - b0 < NBC) ? (NB - b0) : NBC;

    const int gp  = lane >> 2;           // D-frag row (= batch) 0..7
    const int tig = lane & 3;
    // mma role: warp owns n8 tiles cb0, cb0+1 (16 gate cols)
    const int cb0 = wid * 2;
    // epilogue role: one cell per thread (tid < 896)
    const int uu = tid & 127;
    const int jj = tid >> 7;             // 0..7
    const bool vld = (jj < nb);

    const uint2* __restrict__ WRp = reinterpret_cast<const uint2*>(WR);

    // zero both A buffers (h starts at 0; pad rows stay 0)
    for (int i = tid; i < 2 * 16 * 136 / 2; i += 1024)
        reinterpret_cast<uint32_t*>(&A[0][0])[i] = 0u;
    __syncthreads();

    const int lrow = (lane & 7) + ((lane >> 3) & 1) * 8;
    const int kadd = (lane >> 4) * 8;
    const uint32_t Ab0 = smem_u32(&A[0][0]);
    const uint32_t Ab1 = smem_u32(&A[1][0]);

    // preload xp for t=0 (this thread's single cell)
    uint2 xa = make_uint2(0u, 0u);
    if (vld)
        xa = *reinterpret_cast<const uint2*>(
            &xp[((size_t)(b0 + jj) * NT + 0) * 512 + uu * 4]);

    float cst = 0.f;
    int p = 0;

    for (int t = 0; t < NT; ++t) {
        // ---- prefetch xp for t+1 ----
        uint2 nx = make_uint2(0u, 0u);
        if (t + 1 < NT && vld)
            nx = *reinterpret_cast<const uint2*>(
                &xp[((size_t)(b0 + jj) * NT + (t + 1)) * 512 + uu * 4]);

        // ---- W_hh * h via mma.sync (fp32 acc), B-frags streamed from gmem ----
        float acc[2][4];
#pragma unroll
        for (int nt = 0; nt < 2; ++nt)
#pragma unroll
            for (int i = 0; i < 4; ++i) acc[nt][i] = 0.f;

        const uint32_t Ab = p ? Ab1 : Ab0;
#pragma unroll
        for (int ks = 0; ks < 8; ++ks) {
            uint2 bf0 = WRp[(size_t)((cb0 + 0) * 8 + ks) * 32 + lane];
            uint2 bf1 = WRp[(size_t)((cb0 + 1) * 8 + ks) * 32 + lane];
            uint32_t addr = Ab + (uint32_t)(lrow * 136 + ks * 16 + kadd) * 2;
            uint32_t a0, a1, a2, a3;
            asm volatile("ldmatrix.sync.aligned.m8n8.x4.shared.b16 {%0,%1,%2,%3}, [%4];"
                         : "=r"(a0), "=r"(a1), "=r"(a2), "=r"(a3) : "r"(addr));
            asm volatile(
                "mma.sync.aligned.m16n8k16.row.col.f32.f16.f16.f32 "
                "{%0,%1,%2,%3}, {%4,%5,%6,%7}, {%8,%9}, {%0,%1,%2,%3};"
                : "+f"(acc[0][0]), "+f"(acc[0][1]), "+f"(acc[0][2]), "+f"(acc[0][3])
                : "r"(a0), "r"(a1), "r"(a2), "r"(a3), "r"(bf0.x), "r"(bf0.y));
            asm volatile(
                "mma.sync.aligned.m16n8k16.row.col.f32.f16.f16.f32 "
                "{%0,%1,%2,%3}, {%4,%5,%6,%7}, {%8,%9}, {%0,%1,%2,%3};"
                : "+f"(acc[1][0]), "+f"(acc[1][1]), "+f"(acc[1][2]), "+f"(acc[1][3])
                : "r"(a0), "r"(a1), "r"(a2), "r"(a3), "r"(bf1.x), "r"(bf1.y));
        }

        // ---- store D rows 0..7 (row gp) to Dsm as fp16 ----
#pragma unroll
        for (int nt = 0; nt < 2; ++nt) {
            __half2 d = __floats2half2_rn(acc[nt][0], acc[nt][1]);
            *reinterpret_cast<__half2*>(&Dsm[gp * 520 + (cb0 + nt) * 8 + tig * 2]) = d;
        }
        __syncthreads();

        // ---- epilogue: one cell (batch jj, unit uu) per thread ----
        __half* An = p ? &A[0][0] : &A[1][0];
        if (tid < 896) {
            uint2 d2 = *reinterpret_cast<const uint2*>(&Dsm[jj * 520 + uu * 4]);
            float2 r01 = __half22float2(reinterpret_cast<const __half2*>(&d2)[0]);
            float2 r23 = __half22float2(reinterpret_cast<const __half2*>(&d2)[1]);
            float2 x01 = __half22float2(reinterpret_cast<const __half2*>(&xa)[0]);
            float2 x23 = __half22float2(reinterpret_cast<const __half2*>(&xa)[1]);
            float gi = r01.x + x01.x;
            float gf = r01.y + x01.y;
            float gg = r23.x + x23.x;
            float go = r23.y + x23.y;
            float ii = fast_sig(gi);
            float ff = fast_sig(gf);
            float gz = fast_tanh(gg);
            float oo = fast_sig(go);
            float cn = fmaf(ff, cst, ii * gz);
            cst = cn;
            float hn = oo * fast_tanh(cn);
            __half hn16 = __float2half(hn);

            An[jj * 136 + uu] = hn16;
            if (hout && vld)
                hout[((size_t)(b0 + jj) * NT + t) * NH + uu] = hn16;
            if (hlast && vld && t == NT - 1)
                hlast[(b0 + jj) * NH + uu] = hn;
        }

        xa = nx;
        __syncthreads();
        p ^= 1;
    }
}

// ---------------- final FC on last timestep of layer 2 ----------------
__global__ void fc_kernel(const float* __restrict__ fc_w,
                          const float* __restrict__ fc_b,
                          float* __restrict__ out)
{
    int b = blockIdx.x;
    int tid = threadIdx.x;
    float p = g_hlast[b * NH + tid] * fc_w[tid];
#pragma unroll
    for (int o = 16; o; o >>= 1) p += __shfl_down_sync(0xffffffffu, p, o);
    __shared__ float ws[4];
    if ((tid & 31) == 0) ws[tid >> 5] = p;
    __syncthreads();
    if (tid == 0) out[b] = ws[0] + ws[1] + ws[2] + ws[3] + fc_b[0];
}

// ---------------- launch ----------------
extern "C" void kernel_launch(void* const* d_in, const int* in_sizes, int n_in,
                              void* d_out, int out_size)
{
    const float* x    = (const float*)d_in[0];
    const float* wih0 = (const float*)d_in[1];
    const float* whh0 = (const float*)d_in[2];
    const float* bih0 = (const float*)d_in[3];
    const float* bhh0 = (const float*)d_in[4];
    const float* wih1 = (const float*)d_in[5];
    const float* whh1 = (const float*)d_in[6];
    const float* bih1 = (const float*)d_in[7];
    const float* bhh1 = (const float*)d_in[8];
    const float* wih2 = (const float*)d_in[9];
    const float* whh2 = (const float*)d_in[10];
    const float* bih2 = (const float*)d_in[11];
    const float* bhh2 = (const float*)d_in[12];
    const float* fcw  = (const float*)d_in[13];
    const float* fcb  = (const float*)d_in[14];
    float* out = (float*)d_out;

    void *ph0, *ph1, *phl, *pxp, *pwf, *pwr, *pbias, *pw0;
    cudaGetSymbolAddress(&ph0, g_h0);
    cudaGetSymbolAddress(&ph1, g_h1);
    cudaGetSymbolAddress(&phl, g_hlast);
    cudaGetSymbolAddress(&pxp, g_xph);
    cudaGetSymbolAddress(&pwf, g_WF);
    cudaGetSymbolAddress(&pwr, g_WR);
    cudaGetSymbolAddress(&pbias, g_biasxp);
    cudaGetSymbolAddress(&pw0, g_w0p);

    __half* h0   = (__half*)ph0;
    __half* h1   = (__half*)ph1;
    float*  hl   = (float*)phl;
    __half* xp   = (__half*)pxp;
    __half* WF   = (__half*)pwf;
    __half* WR   = (__half*)pwr;
    float*  bs   = (float*)pbias;
    float*  w0p  = (float*)pw0;

    const int rec_grid = (NB + NBC - 1) / NBC;   // 147

    // prep
    prep_l0_kernel <<<64, 256>>>(wih0, bih0, bhh0, w0p, bs + 0 * 512);
    prep_mma_kernel<<<132, 256>>>(whh0, bih0, bhh0, WR + 0 * 65536, bs + 0 * 512);
    prep_mma_kernel<<<132, 256>>>(wih1, bih1, bhh1, WF + 0 * 65536, bs + 1 * 512);
    prep_mma_kernel<<<132, 256>>>(whh1, bih1, bhh1, WR + 1 * 65536, bs + 1 * 512);
    prep_mma_kernel<<<132, 256>>>(wih2, bih2, bhh2, WF + 1 * 65536, bs + 2 * 512);
    prep_mma_kernel<<<132, 256>>>(whh2, bih2, bhh2, WR + 2 * 65536, bs + 2 * 512);

    // layer 0
    xp0_kernel<<<BT / 128, 512>>>(x, w0p, bs + 0 * 512, xp);
    rec_mma_kernel<<<rec_grid, 1024>>>(xp, WR + 0 * 65536, h0, nullptr);

    // layer 1
    {
        dim3 g(BT / 128, 2);
        xp_mma_kernel<<<g, 512>>>(h0, WF + 0 * 65536, bs + 1 * 512, xp);
    }
    rec_mma_kernel<<<rec_grid, 1024>>>(xp, WR + 1 * 65536, h1, nullptr);

    // layer 2
    {
        dim3 g(BT / 128, 2);
        xp_mma_kernel<<<g, 512>>>(h1, WF + 1 * 65536, bs + 2 * 512, xp);
    }
    rec_mma_kernel<<<rec_grid, 1024>>>(xp, WR + 2 * 65536, nullptr, hl);

    fc_kernel<<<NB, 128>>>(fcw, fcb, out);
}